// round 1
// baseline (speedup 1.0000x reference)
#include <cuda_runtime.h>
#include <cstdint>

#define T_LEN 6000
#define BATCH 64
#define HID   128
#define PROJ  32
#define G4    512   // 4*HID

// ---------------- scratch (no allocs allowed) ----------------
__device__ float g_xi[(size_t)T_LEN * BATCH * G4];   // reused for layer0 and layer1 inputs
__device__ float g_h0[(size_t)T_LEN * BATCH * PROJ]; // layer0 projected outputs
__device__ float g_h1[(size_t)T_LEN * BATCH * PROJ]; // layer1 projected outputs

__device__ __forceinline__ float sigmoidf_(float x) {
    return __fdividef(1.f, 1.f + __expf(-x));
}
__device__ __forceinline__ float tanhf_(float x) {
    // 1 - 2/(e^{2x}+1); stable at both extremes with __expf (inf -> 1, 0 -> -1)
    return 1.f - __fdividef(2.f, __expf(2.f * x) + 1.f);
}

// ---------------- GEMM0: xi[t][b][g] = bias[g] + sum_f Wih[g][f] * x[b][f][t] ----
__global__ void __launch_bounds__(512, 1) gemm_xi0(
    const float* __restrict__ x, const float* __restrict__ Wih,
    const float* __restrict__ bih, const float* __restrict__ bhh,
    float* __restrict__ xi)
{
    int b  = blockIdx.y;
    int t0 = blockIdx.x * 128;
    int g  = threadIdx.x;

    __shared__ float4 xs[80][32];   // [f][t/4] tile of x, 40KB

    for (int idx = g; idx < 80 * 32; idx += 512) {
        int f = idx >> 5, i4 = idx & 31;
        int t = t0 + i4 * 4;
        const float* src = x + ((size_t)b * 80 + f) * T_LEN + t;
        float4 v;
        if (t + 3 < T_LEN) {
            v = *reinterpret_cast<const float4*>(src);
        } else {
            v.x = (t     < T_LEN) ? src[0] : 0.f;
            v.y = (t + 1 < T_LEN) ? src[1] : 0.f;
            v.z = (t + 2 < T_LEN) ? src[2] : 0.f;
            v.w = (t + 3 < T_LEN) ? src[3] : 0.f;
        }
        xs[f][i4] = v;
    }

    float w[80];
#pragma unroll
    for (int f = 0; f < 80; f++) w[f] = Wih[g * 80 + f];
    float bias = bih[g] + bhh[g];
    __syncthreads();

    int tmax = min(128, T_LEN - t0);
    for (int i = 0; i < tmax; i += 4) {
        float a0 = bias, a1 = bias, a2 = bias, a3 = bias;
#pragma unroll
        for (int f = 0; f < 80; f++) {
            float4 v = xs[f][i >> 2];
            float wf = w[f];
            a0 += wf * v.x; a1 += wf * v.y; a2 += wf * v.z; a3 += wf * v.w;
        }
        size_t o = ((size_t)(t0 + i) * BATCH + b) * G4 + g;
        xi[o] = a0;
        if (i + 1 < tmax) xi[o + (size_t)BATCH * G4]     = a1;
        if (i + 2 < tmax) xi[o + (size_t)2 * BATCH * G4] = a2;
        if (i + 3 < tmax) xi[o + (size_t)3 * BATCH * G4] = a3;
    }
}

// ---------------- GEMM1: xi[t][b][g] = bias[g] + sum_{j<32} Wih[g][j] * h0[t][b][j] ----
__global__ void __launch_bounds__(512, 1) gemm_xi1(
    const float* __restrict__ h0, const float* __restrict__ Wih,
    const float* __restrict__ bih, const float* __restrict__ bhh,
    float* __restrict__ xi)
{
    int b  = blockIdx.y;
    int t0 = blockIdx.x * 128;
    int g  = threadIdx.x;

    __shared__ float4 hs[128][8];   // [t][j/4] tile of h0, 16KB
    int tmax = min(128, T_LEN - t0);

    for (int idx = g; idx < 128 * 8; idx += 512) {
        int i = idx >> 3, j4 = idx & 7;
        float4 v = make_float4(0.f, 0.f, 0.f, 0.f);
        if (i < tmax)
            v = *reinterpret_cast<const float4*>(
                    h0 + ((size_t)(t0 + i) * BATCH + b) * PROJ + j4 * 4);
        hs[i][j4] = v;
    }

    float w[32];
#pragma unroll
    for (int j = 0; j < 32; j++) w[j] = Wih[g * 32 + j];
    float bias = bih[g] + bhh[g];
    __syncthreads();

    for (int i = 0; i < tmax; i += 2) {
        float a0 = bias, a1 = bias;
#pragma unroll
        for (int j4 = 0; j4 < 8; j4++) {
            float4 v0 = hs[i][j4];
            float4 v1 = hs[i + 1][j4];
            a0 += w[j4*4+0]*v0.x + w[j4*4+1]*v0.y + w[j4*4+2]*v0.z + w[j4*4+3]*v0.w;
            a1 += w[j4*4+0]*v1.x + w[j4*4+1]*v1.y + w[j4*4+2]*v1.z + w[j4*4+3]*v1.w;
        }
        size_t o = ((size_t)(t0 + i) * BATCH + b) * G4 + g;
        xi[o] = a0;
        if (i + 1 < tmax) xi[o + (size_t)BATCH * G4] = a1;
    }
}

// ---------------- sequential LSTM scan: one block per batch element ----------------
// thread j owns cell j: gates i/f/g/o live in rows j, 128+j, 256+j, 384+j of Whh.
__global__ void __launch_bounds__(128, 1) lstm_scan(
    const float* __restrict__ xi,
    const float* __restrict__ Whh,   // [512][32]
    const float* __restrict__ Whr,   // [32][128]
    float* __restrict__ hsout)       // [T][B][32]
{
    int b    = blockIdx.x;
    int tid  = threadIdx.x;
    int lane = tid & 31, warp = tid >> 5;

    // Whh rows for my 4 gates, in registers
    float whh[4][32];
#pragma unroll
    for (int q = 0; q < 4; q++)
#pragma unroll
        for (int j = 0; j < 32; j++)
            whh[q][j] = Whh[(q * HID + tid) * PROJ + j];

    // projection slice: thread (warp,lane) contributes sum_{i} Whr[lane][warp*32+i]*ot[warp*32+i]
    float whr[32];
#pragma unroll
    for (int i = 0; i < 32; i++)
        whr[i] = Whr[lane * HID + warp * 32 + i];

    __shared__ float h_sm[PROJ];
    __shared__ float ot_sm[HID];
    __shared__ float hp_sm[4][PROJ];

    float c = 0.f;
    if (tid < PROJ) h_sm[tid] = 0.f;
    __syncthreads();

    const size_t strideT = (size_t)BATCH * G4;
    const float* xp = xi + (size_t)b * G4 + tid;

    // software-pipelined xi loads (one step of lookahead)
    float nx0 = xp[0], nx1 = xp[HID], nx2 = xp[2 * HID], nx3 = xp[3 * HID];

    for (int t = 0; t < T_LEN; t++) {
        float gi = nx0, gf = nx1, gg = nx2, go = nx3;
        if (t + 1 < T_LEN) {
            const float* xn = xp + (size_t)(t + 1) * strideT;
            nx0 = xn[0]; nx1 = xn[HID]; nx2 = xn[2 * HID]; nx3 = xn[3 * HID];
        }

#pragma unroll
        for (int j = 0; j < 32; j++) {
            float hv = h_sm[j];
            gi += whh[0][j] * hv;
            gf += whh[1][j] * hv;
            gg += whh[2][j] * hv;
            go += whh[3][j] * hv;
        }

        float iv = sigmoidf_(gi);
        float fv = sigmoidf_(gf);
        float gv = tanhf_(gg);
        float ov = sigmoidf_(go);
        c = fv * c + iv * gv;
        float ot = ov * tanhf_(c);

        ot_sm[tid] = ot;
        __syncthreads();

        // projection partials: warp w covers ot indices [32w, 32w+32), output k=lane
        float acc = 0.f;
#pragma unroll
        for (int i = 0; i < 32; i++)
            acc += whr[i] * ot_sm[warp * 32 + i];
        hp_sm[warp][lane] = acc;
        __syncthreads();

        if (tid < PROJ) {
            float hk = hp_sm[0][tid] + hp_sm[1][tid] + hp_sm[2][tid] + hp_sm[3][tid];
            h_sm[tid] = hk;
            hsout[((size_t)t * BATCH + b) * PROJ + tid] = hk;
        }
        __syncthreads();
    }
}

// ---------------- head: out[b][t] = sigmoid(relu(relu(h1) @ W2^T + b2)) ----------------
__global__ void head_kernel(
    const float* __restrict__ hs1,
    const float* __restrict__ W2, const float* __restrict__ b2,
    float* __restrict__ out)
{
    int idx = blockIdx.x * 256 + threadIdx.x;   // idx = b*T + t
    if (idx >= BATCH * T_LEN) return;
    int bb = idx / T_LEN, t = idx - bb * T_LEN;
    const float4* h = reinterpret_cast<const float4*>(
        hs1 + ((size_t)t * BATCH + bb) * PROJ);
    float acc = __ldg(b2);
#pragma unroll
    for (int j4 = 0; j4 < 8; j4++) {
        float4 v = h[j4];
        acc += fmaxf(v.x, 0.f) * __ldg(W2 + j4 * 4 + 0)
             + fmaxf(v.y, 0.f) * __ldg(W2 + j4 * 4 + 1)
             + fmaxf(v.z, 0.f) * __ldg(W2 + j4 * 4 + 2)
             + fmaxf(v.w, 0.f) * __ldg(W2 + j4 * 4 + 3);
    }
    acc = fmaxf(acc, 0.f);
    out[idx] = __fdividef(1.f, 1.f + __expf(-acc));
}

// ---------------- launch ----------------
extern "C" void kernel_launch(void* const* d_in, const int* in_sizes, int n_in,
                              void* d_out, int out_size)
{
    const float* x    = (const float*)d_in[0];
    const float* Wih0 = (const float*)d_in[1];
    const float* Whh0 = (const float*)d_in[2];
    const float* bih0 = (const float*)d_in[3];
    const float* bhh0 = (const float*)d_in[4];
    const float* Whr0 = (const float*)d_in[5];
    const float* Wih1 = (const float*)d_in[6];
    const float* Whh1 = (const float*)d_in[7];
    const float* bih1 = (const float*)d_in[8];
    const float* bhh1 = (const float*)d_in[9];
    const float* Whr1 = (const float*)d_in[10];
    const float* W2   = (const float*)d_in[11];
    const float* b2   = (const float*)d_in[12];
    float* out = (float*)d_out;

    float *xi, *h0, *h1;
    cudaGetSymbolAddress((void**)&xi, g_xi);
    cudaGetSymbolAddress((void**)&h0, g_h0);
    cudaGetSymbolAddress((void**)&h1, g_h1);

    dim3 gridG((T_LEN + 127) / 128, BATCH);   // 47 x 64

    gemm_xi0<<<gridG, 512>>>(x, Wih0, bih0, bhh0, xi);
    lstm_scan<<<BATCH, 128>>>(xi, Whh0, Whr0, h0);
    gemm_xi1<<<gridG, 512>>>(h0, Wih1, bih1, bhh1, xi);
    lstm_scan<<<BATCH, 128>>>(xi, Whh1, Whr1, h1);
    head_kernel<<<(BATCH * T_LEN + 255) / 256, 256>>>(h1, W2, b2, out);
}

// round 2
// speedup vs baseline: 1.2420x; 1.2420x over previous
#include <cuda_runtime.h>
#include <cstdint>

#define T_LEN 6000
#define BATCH 64
#define HID   128
#define PROJ  32
#define G4    512   // 4*HID

typedef unsigned long long u64;

// ---------------- scratch ----------------
__device__ float g_xi[(size_t)T_LEN * BATCH * G4];   // layer0 input transform

// ---------------- f32x2 helpers (Blackwell packed fp32) ----------------
__device__ __forceinline__ u64 pk(float lo, float hi) {
    u64 r;
    asm("mov.b64 %0, {%1, %2};" : "=l"(r) : "f"(lo), "f"(hi));
    return r;
}
__device__ __forceinline__ void upk(u64 a, float& lo, float& hi) {
    asm("mov.b64 {%0, %1}, %2;" : "=f"(lo), "=f"(hi) : "l"(a));
}
__device__ __forceinline__ void fma2(u64& d, u64 a, u64 b) {
    asm("fma.rn.f32x2 %0, %1, %2, %3;" : "=l"(d) : "l"(a), "l"(b), "l"(d));
}
__device__ __forceinline__ float hsum(u64 a) {
    float lo, hi; upk(a, lo, hi); return lo + hi;
}

__device__ __forceinline__ float sigm(float x) {
    return __fdividef(1.f, 1.f + __expf(-x));
}
__device__ __forceinline__ float tanh_(float x) {
    return 1.f - __fdividef(2.f, __expf(2.f * x) + 1.f);
}

// ---------------- GEMM0: xi[t][b][g] = bias[g] + sum_f Wih[g][f] * x[b][f][t] ----
__global__ void __launch_bounds__(512, 1) gemm_xi0(
    const float* __restrict__ x, const float* __restrict__ Wih,
    const float* __restrict__ bih, const float* __restrict__ bhh,
    float* __restrict__ xi)
{
    int b  = blockIdx.y;
    int t0 = blockIdx.x * 128;
    int g  = threadIdx.x;

    __shared__ u64 xs2[80][64];   // packed (t,t+1) pairs, 40KB

    for (int idx = g; idx < 80 * 32; idx += 512) {
        int f = idx >> 5, i4 = idx & 31;
        int t = t0 + i4 * 4;
        const float* src = x + ((size_t)b * 80 + f) * T_LEN + t;
        float4 v;
        if (t + 3 < T_LEN) {
            v = *reinterpret_cast<const float4*>(src);
        } else {
            v.x = (t     < T_LEN) ? src[0] : 0.f;
            v.y = (t + 1 < T_LEN) ? src[1] : 0.f;
            v.z = (t + 2 < T_LEN) ? src[2] : 0.f;
            v.w = (t + 3 < T_LEN) ? src[3] : 0.f;
        }
        xs2[f][i4 * 2]     = pk(v.x, v.y);
        xs2[f][i4 * 2 + 1] = pk(v.z, v.w);
    }

    float w[80];
#pragma unroll
    for (int f = 0; f < 80; f++) w[f] = Wih[g * 80 + f];
    float bias = bih[g] + bhh[g];
    __syncthreads();

    int tmax = min(128, T_LEN - t0);   // 128 or 112, both multiples of 8
    const size_t st = (size_t)BATCH * G4;

    for (int i8 = 0; i8 < tmax / 8; i8++) {
        u64 a0 = pk(bias, bias), a1 = a0, a2 = a0, a3 = a0;
#pragma unroll
        for (int f = 0; f < 80; f++) {
            u64 pA, pB, pC, pD;
            uint32_t sa = (uint32_t)__cvta_generic_to_shared(&xs2[f][i8 * 4]);
            asm("ld.shared.v2.u64 {%0, %1}, [%2];"    : "=l"(pA), "=l"(pB) : "r"(sa));
            asm("ld.shared.v2.u64 {%0, %1}, [%2+16];" : "=l"(pC), "=l"(pD) : "r"(sa));
            u64 w2 = pk(w[f], w[f]);
            fma2(a0, w2, pA); fma2(a1, w2, pB);
            fma2(a2, w2, pC); fma2(a3, w2, pD);
        }
        size_t o = ((size_t)(t0 + i8 * 8) * BATCH + b) * G4 + g;
        float lo, hi;
        upk(a0, lo, hi); xi[o]          = lo; xi[o + st]     = hi;
        upk(a1, lo, hi); xi[o + 2 * st] = lo; xi[o + 3 * st] = hi;
        upk(a2, lo, hi); xi[o + 4 * st] = lo; xi[o + 5 * st] = hi;
        upk(a3, lo, hi); xi[o + 6 * st] = lo; xi[o + 7 * st] = hi;
    }
}

// ---------------- fused pipelined scan: layer0 + (Wih1·h0) + layer1 + head ----
// one block per batch. 384 threads:
//   grp0 (warps 0-3):  layer-0 cells, thread u owns cell u (gates u, 128+u, 256+u, 384+u)
//   grp1 (warps 4-7):  xi1[t] = Wih1·h0[t] + bias1, one step behind
//   grp2 (warps 8-11): layer-1 cells, two steps behind; emits final output
__global__ void __launch_bounds__(384, 1) fused_scan(
    const float* __restrict__ xi0,
    const float* __restrict__ Whh0, const float* __restrict__ Whr0,
    const float* __restrict__ Wih1,
    const float* __restrict__ bih1, const float* __restrict__ bhh1,
    const float* __restrict__ Whh1, const float* __restrict__ Whr1,
    const float* __restrict__ W2,   const float* __restrict__ b2,
    float* __restrict__ out)
{
    const int b   = blockIdx.x;
    const int tid = threadIdx.x;
    const int grp = tid >> 7;          // 0,1,2
    const int u   = tid & 127;
    const int w   = u >> 5, l = u & 31;

    __shared__ __align__(16) float h0buf[2][32];
    __shared__ __align__(16) float xi1buf[2][512];
    __shared__ __align__(16) float h1st[32];
    __shared__ __align__(16) float ot0s[128];
    __shared__ __align__(16) float ot1s[128];
    __shared__ float hp0[4][32];
    __shared__ float hp1[4][32];
    __shared__ u64 whr0s[4][16][32];   // [warp][i][lane] packed Whr pairs
    __shared__ u64 whr1s[4][16][32];

    u64   wgt[4][16];      // per-thread packed weight rows (Whh0 / Wih1 / Whh1)
    float bias1q[4];
    float c = 0.f;
    float w2v = 0.f, b2v = 0.f;

    if (grp == 0) {
#pragma unroll
        for (int q = 0; q < 4; q++) {
            const u64* p = reinterpret_cast<const u64*>(Whh0 + (q * HID + u) * PROJ);
#pragma unroll
            for (int j = 0; j < 16; j++) wgt[q][j] = p[j];
        }
        const u64* wr = reinterpret_cast<const u64*>(Whr0 + l * HID + w * 32);
#pragma unroll
        for (int i = 0; i < 16; i++) whr0s[w][i][l] = wr[i];
        if (u < 32)       h0buf[0][u]      = 0.f;
        else if (u < 64)  h0buf[1][u - 32] = 0.f;
    } else if (grp == 1) {
#pragma unroll
        for (int q = 0; q < 4; q++) {
            const u64* p = reinterpret_cast<const u64*>(Wih1 + (q * HID + u) * PROJ);
#pragma unroll
            for (int j = 0; j < 16; j++) wgt[q][j] = p[j];
            bias1q[q] = bih1[q * HID + u] + bhh1[q * HID + u];
        }
    } else {
#pragma unroll
        for (int q = 0; q < 4; q++) {
            const u64* p = reinterpret_cast<const u64*>(Whh1 + (q * HID + u) * PROJ);
#pragma unroll
            for (int j = 0; j < 16; j++) wgt[q][j] = p[j];
        }
        const u64* wr = reinterpret_cast<const u64*>(Whr1 + l * HID + w * 32);
#pragma unroll
        for (int i = 0; i < 16; i++) whr1s[w][i][l] = wr[i];
        if (u < 32) { h1st[u] = 0.f; w2v = W2[u]; b2v = b2[0]; }
    }
    __syncthreads();

    // grp0: 2-deep xi0 prefetch
    const size_t strideT = (size_t)BATCH * G4;
    const float* xp = xi0 + (size_t)b * G4 + u;
    float cur[4], nxt[4];
    if (grp == 0) {
#pragma unroll
        for (int q = 0; q < 4; q++) cur[q] = __ldcs(xp + q * HID);
#pragma unroll
        for (int q = 0; q < 4; q++) nxt[q] = __ldcs(xp + strideT + q * HID);
    }

    for (int s = 0; s < T_LEN + 2; s++) {
        if (grp == 0) {
            if (s < T_LEN) {
                u64 a0 = pk(cur[0], 0.f), a1 = pk(cur[1], 0.f);
                u64 a2 = pk(cur[2], 0.f), a3 = pk(cur[3], 0.f);
#pragma unroll
                for (int q = 0; q < 4; q++) cur[q] = nxt[q];
                if (s + 2 < T_LEN) {
                    const float* xn = xp + (size_t)(s + 2) * strideT;
#pragma unroll
                    for (int q = 0; q < 4; q++) nxt[q] = __ldcs(xn + q * HID);
                }
                const u64* h2 = reinterpret_cast<const u64*>(h0buf[(s + 1) & 1]);
#pragma unroll
                for (int j = 0; j < 16; j++) {
                    u64 hv = h2[j];
                    fma2(a0, wgt[0][j], hv);
                    fma2(a1, wgt[1][j], hv);
                    fma2(a2, wgt[2][j], hv);
                    fma2(a3, wgt[3][j], hv);
                }
                float iv = sigm(hsum(a0));
                float fv = sigm(hsum(a1));
                float gv = tanh_(hsum(a2));
                float ov = sigm(hsum(a3));
                c = fv * c + iv * gv;
                float ot = ov * tanh_(c);
                ot0s[u] = ot;
                asm volatile("bar.sync 1, 128;" ::: "memory");
                const u64* o2 = reinterpret_cast<const u64*>(ot0s) + w * 16;
                u64 pc = pk(0.f, 0.f);
#pragma unroll
                for (int i = 0; i < 16; i++) fma2(pc, whr0s[w][i][l], o2[i]);
                hp0[w][l] = hsum(pc);
                asm volatile("bar.sync 1, 128;" ::: "memory");
                if (u < 32)
                    h0buf[s & 1][u] = hp0[0][u] + hp0[1][u] + hp0[2][u] + hp0[3][u];
            }
        } else if (grp == 1) {
            if (s >= 1 && s <= T_LEN) {
                const u64* h2 = reinterpret_cast<const u64*>(h0buf[(s - 1) & 1]);
                u64 a0 = pk(0.f, 0.f), a1 = a0, a2 = a0, a3 = a0;
#pragma unroll
                for (int j = 0; j < 16; j++) {
                    u64 hv = h2[j];
                    fma2(a0, wgt[0][j], hv);
                    fma2(a1, wgt[1][j], hv);
                    fma2(a2, wgt[2][j], hv);
                    fma2(a3, wgt[3][j], hv);
                }
                float* xo = xi1buf[(s - 1) & 1];
                xo[u]           = bias1q[0] + hsum(a0);
                xo[HID + u]     = bias1q[1] + hsum(a1);
                xo[2 * HID + u] = bias1q[2] + hsum(a2);
                xo[3 * HID + u] = bias1q[3] + hsum(a3);
            }
        } else {
            if (s >= 2) {
                const float* xq = xi1buf[s & 1];
                u64 a0 = pk(xq[u],           0.f);
                u64 a1 = pk(xq[HID + u],     0.f);
                u64 a2 = pk(xq[2 * HID + u], 0.f);
                u64 a3 = pk(xq[3 * HID + u], 0.f);
                const u64* h2 = reinterpret_cast<const u64*>(h1st);
#pragma unroll
                for (int j = 0; j < 16; j++) {
                    u64 hv = h2[j];
                    fma2(a0, wgt[0][j], hv);
                    fma2(a1, wgt[1][j], hv);
                    fma2(a2, wgt[2][j], hv);
                    fma2(a3, wgt[3][j], hv);
                }
                float iv = sigm(hsum(a0));
                float fv = sigm(hsum(a1));
                float gv = tanh_(hsum(a2));
                float ov = sigm(hsum(a3));
                c = fv * c + iv * gv;
                float ot = ov * tanh_(c);
                ot1s[u] = ot;
                asm volatile("bar.sync 2, 128;" ::: "memory");
                const u64* o2 = reinterpret_cast<const u64*>(ot1s) + w * 16;
                u64 pc = pk(0.f, 0.f);
#pragma unroll
                for (int i = 0; i < 16; i++) fma2(pc, whr1s[w][i][l], o2[i]);
                hp1[w][l] = hsum(pc);
                asm volatile("bar.sync 2, 128;" ::: "memory");
                if (u < 32) {
                    float h1v = hp1[0][u] + hp1[1][u] + hp1[2][u] + hp1[3][u];
                    h1st[u] = h1v;
                    // head: sigmoid(relu(relu(h1)·W2 + b2))
                    float val = fmaxf(h1v, 0.f) * w2v;
#pragma unroll
                    for (int off = 16; off; off >>= 1)
                        val += __shfl_down_sync(0xffffffffu, val, off);
                    if (u == 0) {
                        float z = fmaxf(val + b2v, 0.f);
                        out[(size_t)b * T_LEN + (s - 2)] =
                            __fdividef(1.f, 1.f + __expf(-z));
                    }
                }
            }
        }
        __syncthreads();
    }
}

// ---------------- launch ----------------
extern "C" void kernel_launch(void* const* d_in, const int* in_sizes, int n_in,
                              void* d_out, int out_size)
{
    const float* x    = (const float*)d_in[0];
    const float* Wih0 = (const float*)d_in[1];
    const float* Whh0 = (const float*)d_in[2];
    const float* bih0 = (const float*)d_in[3];
    const float* bhh0 = (const float*)d_in[4];
    const float* Whr0 = (const float*)d_in[5];
    const float* Wih1 = (const float*)d_in[6];
    const float* Whh1 = (const float*)d_in[7];
    const float* bih1 = (const float*)d_in[8];
    const float* bhh1 = (const float*)d_in[9];
    const float* Whr1 = (const float*)d_in[10];
    const float* W2   = (const float*)d_in[11];
    const float* b2   = (const float*)d_in[12];
    float* out = (float*)d_out;

    float* xi;
    cudaGetSymbolAddress((void**)&xi, g_xi);

    dim3 gridG((T_LEN + 127) / 128, BATCH);   // 47 x 64

    gemm_xi0<<<gridG, 512>>>(x, Wih0, bih0, bhh0, xi);
    fused_scan<<<BATCH, 384>>>(xi, Whh0, Whr0,
                               Wih1, bih1, bhh1, Whh1, Whr1,
                               W2, b2, out);
}